// round 15
// baseline (speedup 1.0000x reference)
#include <cuda_runtime.h>
#include <cuda_bf16.h>
#include <cstdint>
#include <math.h>

typedef unsigned char      u8;
typedef unsigned short     u16;
typedef unsigned int       u32;
typedef unsigned long long u64;

// Problem sizes (fixed by reference)
#define BB 1024
#define NN 24
#define LL 24
#define DD 128
#define VV 40000
#define NV 39999      // V-1 output columns
#define ALPHA 0.2f
#define NEGC (-9e15f)

// HMMA tile format
#define NB4 313              // ceil(39999/128) (prep granularity)
#define NB64 625             // ceil(39999/64)  (k4 col blocks)
#define NPAD (NB4*128)       // 40064
#define TSTRIDE 272          // bytes per row (17 x 16B -> conflict-free ldmatrix)
#define TILE_BYTES (128*TSTRIDE)        // 34816 (128-row tile)
#define TILE_U4 (TILE_BYTES/16)         // 2176
#define TILE_U32 (TILE_BYTES/4)         // 8704
#define HTILE_BYTES (64*TSTRIDE)        // 17408 (64-row tile)
#define HTILE_U4 (HTILE_BYTES/16)       // 1088
#define SMEM_HM (2*TILE_BYTES + 2*HTILE_BYTES)   // 104448 -> 2 CTAs/SM

// -------- device scratch (no runtime allocations allowed) --------
__device__ float g_Wci[DD*DD];
__device__ float g_Wct[DD*DD];
__device__ float g_bcomb[DD];
__device__ float g_h[BB*NN*DD];
__device__ float g_seq[BB*LL*DD];
__device__ float g_gate[BB*LL*DD];
__device__ float g_hs[BB*DD];
__device__ float g_hsg[BB*DD];
__device__ float g_select[BB*DD];
// padded bf16 hi/lo tiles
__device__ uint4 g_Bhi4[(size_t)NB4*TILE_U4];
__device__ uint4 g_Blo4[(size_t)NB4*TILE_U4];
__device__ uint4 g_Ahi4[8*TILE_U4];
__device__ uint4 g_Alo4[8*TILE_U4];
// transposed weight tiles for mid GEMMs: [0..2]=k1 (Wfuse0,Wci,Wct), [3..4]=w_1, [5]=glu1_w
__device__ uint4 g_Wt_hi[6*TILE_U4];
__device__ uint4 g_Wt_lo[6*TILE_U4];

// ==================== helpers ====================
__device__ __forceinline__ u32 smem_u32(const void* p) {
    u32 a;
    asm("{ .reg .u64 t; cvta.to.shared.u64 t, %1; cvt.u32.u64 %0, t; }" : "=r"(a) : "l"(p));
    return a;
}
__device__ __forceinline__ void ldsm4(u32* r, u32 addr) {
    asm volatile("ldmatrix.sync.aligned.m8n8.x4.shared.b16 {%0,%1,%2,%3}, [%4];"
        : "=r"(r[0]), "=r"(r[1]), "=r"(r[2]), "=r"(r[3]) : "r"(addr));
}
__device__ __forceinline__ void mma16816(float* c, const u32* a, u32 b0, u32 b1) {
    asm volatile("mma.sync.aligned.m16n8k16.row.col.f32.bf16.bf16.f32 "
        "{%0,%1,%2,%3}, {%4,%5,%6,%7}, {%8,%9}, {%0,%1,%2,%3};"
        : "+f"(c[0]), "+f"(c[1]), "+f"(c[2]), "+f"(c[3])
        : "r"(a[0]), "r"(a[1]), "r"(a[2]), "r"(a[3]), "r"(b0), "r"(b1));
}
__device__ __forceinline__ void split_bf16(float v, u16& h, u16& l) {
    __nv_bfloat16 hb = __float2bfloat16(v);
    float rem = v - __bfloat162float(hb);
    __nv_bfloat16 lb = __float2bfloat16(rem);
    h = __bfloat16_as_ushort(hb);
    l = __bfloat16_as_ushort(lb);
}
__device__ __forceinline__ void split_pair(float v0, float v1, u32& hi, u32& lo) {
    u16 h0, l0, h1, l1;
    split_bf16(v0, h0, l0);
    split_bf16(v1, h1, l1);
    hi = (u32)h0 | ((u32)h1 << 16);
    lo = (u32)l0 | ((u32)l1 << 16);
}

// 32x32 warp tile over K=128 chunk, 3-term split-bf16.
__device__ __forceinline__ void hmma_warp32(u32 sAhi, u32 sAlo, u32 sBhi, u32 sBlo,
                                            int arow, int brow, int lane,
                                            float acc[2][4][4]) {
    u32 aoff = (u32)(arow + (lane & 15)) * TSTRIDE + ((lane >> 4) << 3) * 2;
    u32 boff = (u32)(brow + (lane & 7) + ((lane >> 4) << 3)) * TSTRIDE
             + (((lane >> 3) & 1) << 3) * 2;
#pragma unroll
    for (int ks = 0; ks < 8; ks++) {
        u32 kbyte = (u32)ks * 32;
        u32 bhi[2][4], blo[2][4];
#pragma unroll
        for (int np = 0; np < 2; np++) {
            u32 off = boff + (u32)(np*16)*TSTRIDE + kbyte;
            ldsm4(bhi[np], sBhi + off);
            ldsm4(blo[np], sBlo + off);
        }
#pragma unroll
        for (int mi = 0; mi < 2; mi++) {
            u32 ahi[4], alo[4];
            u32 off = aoff + (u32)(mi*16)*TSTRIDE + kbyte;
            ldsm4(ahi, sAhi + off);
            ldsm4(alo, sAlo + off);
#pragma unroll
            for (int ni = 0; ni < 4; ni++) {
                int np = ni >> 1;
                int s = (ni & 1) * 2;
                mma16816(acc[mi][ni], ahi, bhi[np][s], bhi[np][s+1]);
                mma16816(acc[mi][ni], ahi, blo[np][s], blo[np][s+1]);
                mma16816(acc[mi][ni], alo, bhi[np][s], bhi[np][s+1]);
            }
        }
    }
}

// ==================== K0: fold W_img/W_txt into W_fuse ====================
__global__ void k0_combine(const float* __restrict__ W_img, const float* __restrict__ W_txt,
                           const float* __restrict__ W_fuse, const float* __restrict__ b_img,
                           const float* __restrict__ b_txt, const float* __restrict__ b_fuse) {
    int k = blockIdx.x, d = threadIdx.x;
    float s1 = 0.f, s2 = 0.f;
    for (int j = 0; j < DD; j++) {
        s1 += W_img[k*DD + j] * W_fuse[(DD   + j)*DD + d];
        s2 += W_txt[k*DD + j] * W_fuse[(2*DD + j)*DD + d];
    }
    g_Wci[k*DD + d] = s1;
    g_Wct[k*DD + d] = s2;
    if (k == 0) {
        float s = b_fuse[d];
        for (int j = 0; j < DD; j++)
            s += b_img[j]*W_fuse[(DD + j)*DD + d] + b_txt[j]*W_fuse[(2*DD + j)*DD + d];
        g_bcomb[d] = s;
    }
}

// ==================== prep: transposed weight tiles (hi/lo) ====================
__global__ void k_prep_W(const float* __restrict__ W_fuse, const float* __restrict__ w_1,
                         const float* __restrict__ glu1_w) {
    int idx = blockIdx.x * 256 + threadIdx.x;
    if (idx >= 6*8192) return;
    int t = idx >> 13;
    int n = (idx >> 6) & 127;
    int c2 = idx & 63;
    int k = c2 * 2;
    float v0, v1;
    switch (t) {
        case 0: v0 = W_fuse[k*DD + n];       v1 = W_fuse[(k+1)*DD + n];       break;
        case 1: v0 = g_Wci[k*DD + n];        v1 = g_Wci[(k+1)*DD + n];        break;
        case 2: v0 = g_Wct[k*DD + n];        v1 = g_Wct[(k+1)*DD + n];        break;
        case 3: v0 = w_1[k*DD + n];          v1 = w_1[(k+1)*DD + n];          break;
        case 4: v0 = w_1[(128+k)*DD + n];    v1 = w_1[(128+k+1)*DD + n];      break;
        default: v0 = glu1_w[k*DD + n];      v1 = glu1_w[(k+1)*DD + n];       break;
    }
    u32 hi, lo;
    split_pair(v0, v1, hi, lo);
    size_t w = (size_t)t * TILE_U32 + (size_t)n * (TSTRIDE/4) + c2;
    reinterpret_cast<u32*>(g_Wt_hi)[w] = hi;
    reinterpret_cast<u32*>(g_Wt_lo)[w] = lo;
}

// ==================== k1: fused multimodal embedding (HMMA, M=64/CTA) ====================
__global__ void __launch_bounds__(256, 2) k_mid(
        const int* __restrict__ items, const float* __restrict__ emb,
        const float* __restrict__ img, const float* __restrict__ txt) {
    extern __shared__ u8 dsm[];
    __shared__ int sitem[64];
    int tid = threadIdx.x;
    int wid = tid >> 5, lane = tid & 31;
    int m0 = blockIdx.x * 64;

    if (tid < 64) sitem[tid] = items[m0 + tid];

    u32 sbase = smem_u32(dsm);
    u32 sAhi = sbase;
    u32 sAlo = sbase + HTILE_BYTES;
    u32 sWhi = sbase + 2*HTILE_BYTES;
    u32 sWlo = sbase + 2*HTILE_BYTES + TILE_BYTES;
    u32* Ahi32 = reinterpret_cast<u32*>(dsm);
    u32* Alo32 = reinterpret_cast<u32*>(dsm + HTILE_BYTES);
    uint4* Wh4 = reinterpret_cast<uint4*>(dsm + 2*HTILE_BYTES);
    uint4* Wl4 = reinterpret_cast<uint4*>(dsm + 2*HTILE_BYTES + TILE_BYTES);

    float acc[2][4][4];
#pragma unroll
    for (int mi = 0; mi < 2; mi++)
#pragma unroll
        for (int ni = 0; ni < 4; ni++)
#pragma unroll
            for (int q = 0; q < 4; q++) acc[mi][ni][q] = 0.f;

    __syncthreads();
    for (int t = 0; t < 3; t++) {
        if (t > 0) __syncthreads();
        {
            const uint4* sh = g_Wt_hi + (size_t)t * TILE_U4;
            const uint4* sl = g_Wt_lo + (size_t)t * TILE_U4;
            for (int i = tid; i < TILE_U4; i += 256) { Wh4[i] = sh[i]; Wl4[i] = sl[i]; }
        }
        const float* src = (t == 0) ? emb : (t == 1) ? img : txt;
        for (int idx = tid; idx < 4096; idx += 256) {
            int r = idx >> 6, c2 = idx & 63, c = c2*2;
            const float* p = src + (size_t)sitem[r]*DD + c;
            u32 hi, lo; split_pair(p[0], p[1], hi, lo);
            int w = r*(TSTRIDE/4) + c2;
            Ahi32[w] = hi; Alo32[w] = lo;
        }
        __syncthreads();
        hmma_warp32(sAhi, sAlo, sWhi, sWlo, (wid >> 2)*32, (wid & 3)*32, lane, acc);
    }
    __syncthreads();

    float* Csm = reinterpret_cast<float*>(dsm);
    {
        int mwarp = wid >> 2, nwarp = wid & 3;
        int grp = lane >> 2, qid = lane & 3;
#pragma unroll
        for (int mi = 0; mi < 2; mi++) {
#pragma unroll
            for (int ni = 0; ni < 4; ni++) {
                int r0 = mwarp*32 + mi*16 + grp;
                int c0 = nwarp*32 + ni*8 + qid*2;
                Csm[r0*132 + c0]       = acc[mi][ni][0];
                Csm[r0*132 + c0 + 1]   = acc[mi][ni][1];
                Csm[(r0+8)*132 + c0]   = acc[mi][ni][2];
                Csm[(r0+8)*132 + c0+1] = acc[mi][ni][3];
            }
        }
    }
    __syncthreads();
    for (int i = tid; i < 64*128; i += 256) {
        int r = i >> 7, c = i & 127;
        g_h[(size_t)(m0 + r)*DD + c] = Csm[r*132 + c] + g_bcomb[c];
    }
}

// ==================== k_mid12: fused nh+gate (2 HMMA GEMMs, nh stays in smem) ====================
__global__ void __launch_bounds__(256, 2) k_mid12(const float* __restrict__ pos_emb) {
    extern __shared__ u8 dsm[];
    int tid = threadIdx.x;
    int wid = tid >> 5, lane = tid & 31;
    int m0 = blockIdx.x * 64;

    u32 sbase = smem_u32(dsm);
    u32 sAhi = sbase;
    u32 sAlo = sbase + HTILE_BYTES;
    u32 sWhi = sbase + 2*HTILE_BYTES;
    u32 sWlo = sbase + 2*HTILE_BYTES + TILE_BYTES;
    u32* Ahi32 = reinterpret_cast<u32*>(dsm);
    u32* Alo32 = reinterpret_cast<u32*>(dsm + HTILE_BYTES);
    uint4* Wh4 = reinterpret_cast<uint4*>(dsm + 2*HTILE_BYTES);
    uint4* Wl4 = reinterpret_cast<uint4*>(dsm + 2*HTILE_BYTES + TILE_BYTES);

    int mwarp = wid >> 2, nwarp = wid & 3;
    int grp = lane >> 2, qid = lane & 3;

    float acc[2][4][4];
#pragma unroll
    for (int mi = 0; mi < 2; mi++)
#pragma unroll
        for (int ni = 0; ni < 4; ni++)
#pragma unroll
            for (int q = 0; q < 4; q++) acc[mi][ni][q] = 0.f;

    // ---- GEMM 1: nh_pre = [pos_rev | seq] @ w_1, two K=128 chunks ----
    for (int t = 0; t < 2; t++) {
        if (t > 0) __syncthreads();
        {
            const uint4* sh = g_Wt_hi + (size_t)(3 + t) * TILE_U4;
            const uint4* sl = g_Wt_lo + (size_t)(3 + t) * TILE_U4;
            for (int i = tid; i < TILE_U4; i += 256) { Wh4[i] = sh[i]; Wl4[i] = sl[i]; }
        }
        for (int idx = tid; idx < 4096; idx += 256) {
            int r = idx >> 6, c2 = idx & 63, c = c2*2;
            int row = m0 + r;
            const float* p;
            if (t == 0) { int l = row % LL; p = pos_emb + (size_t)(LL-1-l)*DD + c; }
            else        { p = g_seq + (size_t)row*DD + c; }
            u32 hi, lo; split_pair(p[0], p[1], hi, lo);
            int w = r*(TSTRIDE/4) + c2;
            Ahi32[w] = hi; Alo32[w] = lo;
        }
        __syncthreads();
        hmma_warp32(sAhi, sAlo, sWhi, sWlo, mwarp*32, nwarp*32, lane, acc);
    }
    __syncthreads();   // all MMA reads of A/W done

    // ---- nh = tanh(acc): split-store fragments directly into A slots; load glu1_w ----
    {
#pragma unroll
        for (int mi = 0; mi < 2; mi++) {
#pragma unroll
            for (int ni = 0; ni < 4; ni++) {
                int r0 = mwarp*32 + mi*16 + grp;
                int c2 = (nwarp*32 + ni*8 + qid*2) >> 1;
                u32 hi, lo;
                split_pair(tanhf(acc[mi][ni][0]), tanhf(acc[mi][ni][1]), hi, lo);
                Ahi32[r0*(TSTRIDE/4) + c2] = hi;
                Alo32[r0*(TSTRIDE/4) + c2] = lo;
                split_pair(tanhf(acc[mi][ni][2]), tanhf(acc[mi][ni][3]), hi, lo);
                Ahi32[(r0+8)*(TSTRIDE/4) + c2] = hi;
                Alo32[(r0+8)*(TSTRIDE/4) + c2] = lo;
            }
        }
        const uint4* sh = g_Wt_hi + (size_t)5 * TILE_U4;
        const uint4* sl = g_Wt_lo + (size_t)5 * TILE_U4;
        for (int i = tid; i < TILE_U4; i += 256) { Wh4[i] = sh[i]; Wl4[i] = sl[i]; }
    }
    __syncthreads();

    // ---- GEMM 2: gate_pre = nh @ glu1_w ----
#pragma unroll
    for (int mi = 0; mi < 2; mi++)
#pragma unroll
        for (int ni = 0; ni < 4; ni++)
#pragma unroll
            for (int q = 0; q < 4; q++) acc[mi][ni][q] = 0.f;
    hmma_warp32(sAhi, sAlo, sWhi, sWlo, mwarp*32, nwarp*32, lane, acc);
    __syncthreads();

    // ---- epilogue: gate = sigmoid(acc + hsg[b]) ----
    float* Csm = reinterpret_cast<float*>(dsm);
    {
#pragma unroll
        for (int mi = 0; mi < 2; mi++) {
#pragma unroll
            for (int ni = 0; ni < 4; ni++) {
                int r0 = mwarp*32 + mi*16 + grp;
                int c0 = nwarp*32 + ni*8 + qid*2;
                Csm[r0*132 + c0]       = acc[mi][ni][0];
                Csm[r0*132 + c0 + 1]   = acc[mi][ni][1];
                Csm[(r0+8)*132 + c0]   = acc[mi][ni][2];
                Csm[(r0+8)*132 + c0+1] = acc[mi][ni][3];
            }
        }
    }
    __syncthreads();
    for (int i = tid; i < 64*128; i += 256) {
        int r = i >> 7, c = i & 127;
        size_t row = (size_t)(m0 + r);
        int b = (int)(row / LL);
        float v = Csm[r*132 + c] + g_hsg[(size_t)b*DD + c];
        g_gate[row*DD + c] = 1.f / (1.f + expf(-v));
    }
}

// ==================== K2: RGAT attention (select-first dot + array butterfly) ====================
__global__ void __launch_bounds__(256, 3) k2_attn(const int* __restrict__ adj,
                        const int* __restrict__ alias_,
                        const int* __restrict__ mask_, const float* __restrict__ a_rel) {
    __shared__ float hsm[NN*DD];
    __shared__ float hag[NN*DD];
    __shared__ float logit[NN*NN];
    __shared__ float arel[4*DD];
    __shared__ int sadj[NN*NN];
    __shared__ int salias[LL];
    __shared__ int smask[LL];
    __shared__ float4 hpart4[256];
    __shared__ float sdenom;
    int b = blockIdx.x, tid = threadIdx.x;
    int wid = tid >> 5, lane = tid & 31;

    {
        const float4* src = reinterpret_cast<const float4*>(&g_h[(size_t)b*NN*DD]);
        float4* dst = reinterpret_cast<float4*>(hsm);
        for (int i = tid; i < NN*DD/4; i += 256) dst[i] = src[i];
        const float4* asrc = reinterpret_cast<const float4*>(a_rel);
        float4* adst = reinterpret_cast<float4*>(arel);
        if (tid < 128) adst[tid] = asrc[tid];
        const int* ja = adj + (size_t)b*NN*NN;
        for (int i = tid; i < NN*NN; i += 256) sadj[i] = ja[i];
    }
    if (tid < LL) { salias[tid] = alias_[b*LL + tid]; smask[tid] = mask_[b*LL + tid]; }
    if (tid == 0) {
        int ms = 0;
        for (int l = 0; l < LL; l++) ms += mask_[b*LL + l];
        sdenom = fmaxf((float)ms, 1.f);
    }
    __syncthreads();

    // ---- edge scores: warp per i; select relation first, one dot per j;
    //      per-lane partials accumulate in a register array, then ONE 5-stage
    //      butterfly reduces all 24 j's simultaneously ----
    {
        const float4* h4 = reinterpret_cast<const float4*>(hsm);
        const float4* a4 = reinterpret_cast<const float4*>(arel);
        for (int i = wid; i < NN; i += 8) {
            float4 hi = h4[i*32 + lane];
            float4 a0 = a4[0*32 + lane], a1 = a4[1*32 + lane];
            float4 a2 = a4[2*32 + lane], a3 = a4[3*32 + lane];
            float4 w0, w1, w2, w3;
            w0.x = hi.x*a0.x; w0.y = hi.y*a0.y; w0.z = hi.z*a0.z; w0.w = hi.w*a0.w;
            w1.x = hi.x*a1.x; w1.y = hi.y*a1.y; w1.z = hi.z*a1.z; w1.w = hi.w*a1.w;
            w2.x = hi.x*a2.x; w2.y = hi.y*a2.y; w2.z = hi.z*a2.z; w2.w = hi.w*a2.w;
            w3.x = hi.x*a3.x; w3.y = hi.y*a3.y; w3.z = hi.z*a3.z; w3.w = hi.w*a3.w;
            float part[NN];
#pragma unroll
            for (int j = 0; j < NN; j++) {
                float4 hj = h4[j*32 + lane];
                int r = sadj[i*NN + j];
                float4 ws = (r == 1) ? w0 : (r == 2) ? w1 : (r == 3) ? w2 : w3;
                part[j] = ws.x*hj.x + ws.y*hj.y + ws.z*hj.z + ws.w*hj.w;
            }
#pragma unroll
            for (int off = 16; off > 0; off >>= 1)
#pragma unroll
                for (int j = 0; j < NN; j++)
                    part[j] += __shfl_xor_sync(0xffffffffu, part[j], off);
#pragma unroll
            for (int j = 0; j < NN; j++) {
                if (lane == j) {
                    int r = sadj[i*NN + j];
                    float e = (part[j] > 0.f) ? part[j] : ALPHA * part[j];
                    logit[i*NN + j] = (r == 0) ? NEGC : e;
                }
            }
        }
    }
    __syncthreads();

    // ---- row softmax ----
    if (tid < NN) {
        float m = -INFINITY;
#pragma unroll
        for (int j = 0; j < NN; j++) m = fmaxf(m, logit[tid*NN + j]);
        float ex[NN]; float ssum = 0.f;
#pragma unroll
        for (int j = 0; j < NN; j++) { ex[j] = __expf(logit[tid*NN + j] - m); ssum += ex[j]; }
        float inv = 1.f / ssum;
#pragma unroll
        for (int j = 0; j < NN; j++) logit[tid*NN + j] = ex[j] * inv;
    }
    __syncthreads();

    // ---- aggregate: hag = att @ h ----
    {
        const float4* h4 = reinterpret_cast<const float4*>(hsm);
        float4* hag4 = reinterpret_cast<float4*>(hag);
        for (int idx = tid; idx < NN*32; idx += 256) {
            int i = idx >> 5;
            int d4 = idx & 31;
            float4 s = make_float4(0.f, 0.f, 0.f, 0.f);
#pragma unroll
            for (int j = 0; j < NN; j++) {
                float w = logit[i*NN + j];
                float4 hv = h4[j*32 + d4];
                s.x += w*hv.x; s.y += w*hv.y; s.z += w*hv.z; s.w += w*hv.w;
            }
            hag4[idx] = s;
        }
    }
    __syncthreads();

    // ---- seq = hag[alias]; hs = masked mean ----
    {
        const float4* hag4 = reinterpret_cast<const float4*>(hag);
        float4* seq4 = reinterpret_cast<float4*>(&g_seq[(size_t)b*LL*DD]);
        float4 part = make_float4(0.f, 0.f, 0.f, 0.f);
        for (int idx = tid; idx < LL*32; idx += 256) {
            int l = idx >> 5;
            int d4 = idx & 31;
            float4 v = hag4[salias[l]*32 + d4];
            seq4[idx] = v;
            float mf = (float)smask[l];
            part.x += v.x*mf; part.y += v.y*mf; part.z += v.z*mf; part.w += v.w*mf;
        }
        hpart4[tid] = part;
    }
    __syncthreads();
    if (tid < 32) {
        float4 s = make_float4(0.f, 0.f, 0.f, 0.f);
#pragma unroll
        for (int w = 0; w < 8; w++) {
            float4 v = hpart4[tid + 32*w];
            s.x += v.x; s.y += v.y; s.z += v.z; s.w += v.w;
        }
        float inv = 1.f / sdenom;
        s.x *= inv; s.y *= inv; s.z *= inv; s.w *= inv;
        reinterpret_cast<float4*>(&g_hs[(size_t)b*DD])[tid] = s;
    }
}

// ==================== K3h: hsg = glu1_b + hs @ glu2_w ====================
__global__ void k3_hsg(const float* __restrict__ glu2_w, const float* __restrict__ glu1_b) {
    __shared__ float shs[DD];
    int b = blockIdx.x, d = threadIdx.x;
    shs[d] = g_hs[(size_t)b*DD + d];
    __syncthreads();
    float s = glu1_b[d];
    for (int k = 0; k < DD; k++) s += shs[k] * glu2_w[k*DD + d];
    g_hsg[(size_t)b*DD + d] = s;
}

// ==================== K3c: beta = gate@w_2 ; select = sum_l beta*seq*mask ====================
__global__ void k3c_select(const int* __restrict__ mask_, const float* __restrict__ w_2) {
    __shared__ float beta[LL];
    __shared__ float sw2[DD];
    __shared__ int smask[LL];
    int b = blockIdx.x, tid = threadIdx.x;
    if (tid < DD) sw2[tid] = w_2[tid];
    if (tid < LL) smask[tid] = mask_[b*LL + tid];
    __syncthreads();
    int wid = tid >> 5, lane = tid & 31;
    for (int l = wid; l < LL; l += 8) {
        float s = 0.f;
        const float* g = &g_gate[((size_t)b*LL + l)*DD];
        for (int d = lane; d < DD; d += 32) s += g[d] * sw2[d];
#pragma unroll
        for (int o = 16; o > 0; o >>= 1) s += __shfl_xor_sync(0xffffffffu, s, o);
        if (lane == 0) beta[l] = s;
    }
    __syncthreads();
    if (tid < DD) {
        float s = 0.f;
        for (int l = 0; l < LL; l++)
            s += beta[l] * (float)smask[l] * g_seq[((size_t)b*LL + l)*DD + tid];
        g_select[(size_t)b*DD + tid] = s;
    }
}

// ==================== prep: emb -> padded bf16 hi/lo tiles ====================
__global__ void k_prep_B(const float* __restrict__ emb) {
    int idx = blockIdx.x * 256 + threadIdx.x;
    if (idx >= NPAD * 64) return;
    int r = idx >> 6;
    int c2 = idx & 63;
    int c = c2 * 2;
    float v0 = 0.f, v1 = 0.f;
    if (r < NV) {
        const float* p = emb + (size_t)(r + 1) * DD + c;
        v0 = p[0]; v1 = p[1];
    }
    u32 hi, lo; split_pair(v0, v1, hi, lo);
    size_t w = (size_t)(r >> 7) * TILE_U32 + (size_t)(r & 127) * (TSTRIDE/4) + c2;
    reinterpret_cast<u32*>(g_Bhi4)[w] = hi;
    reinterpret_cast<u32*>(g_Blo4)[w] = lo;
}

// ==================== prep: select -> padded bf16 hi/lo tiles ====================
__global__ void k_prep_A() {
    int idx = blockIdx.x * 256 + threadIdx.x;
    int row = idx >> 6;
    int c2 = idx & 63;
    int c = c2 * 2;
    float v0 = g_select[(size_t)row * DD + c];
    float v1 = g_select[(size_t)row * DD + c + 1];
    u32 hi, lo; split_pair(v0, v1, hi, lo);
    size_t w = (size_t)(row >> 7) * TILE_U32 + (size_t)(row & 127) * (TSTRIDE/4) + c2;
    reinterpret_cast<u32*>(g_Ahi4)[w] = hi;
    reinterpret_cast<u32*>(g_Alo4)[w] = lo;
}

// ==================== K4: scores GEMM, 128x64 tile, 2 CTAs/SM ====================
__global__ void __launch_bounds__(256, 2) k4_mma(float* __restrict__ out) {
    extern __shared__ u8 dsm[];
    int tid = threadIdx.x;
    int wid = tid >> 5;
    int lane = tid & 31;
    int nb = blockIdx.x;
    int mb = blockIdx.y;

    {
        const uint4* sAh = g_Ahi4 + (size_t)mb * TILE_U4;
        const uint4* sAl = g_Alo4 + (size_t)mb * TILE_U4;
        size_t boffg = (size_t)(nb >> 1) * TILE_U4 + (size_t)(nb & 1) * HTILE_U4;
        const uint4* sBh = g_Bhi4 + boffg;
        const uint4* sBl = g_Blo4 + boffg;
        uint4* dsm4 = reinterpret_cast<uint4*>(dsm);
        for (int i = tid; i < TILE_U4; i += 256) {
            dsm4[i] = sAh[i];
            dsm4[TILE_U4 + i] = sAl[i];
        }
        for (int i = tid; i < HTILE_U4; i += 256) {
            dsm4[2*TILE_U4 + i] = sBh[i];
            dsm4[2*TILE_U4 + HTILE_U4 + i] = sBl[i];
        }
    }
    __syncthreads();

    u32 sbase = smem_u32(dsm);
    float acc[2][4][4];
#pragma unroll
    for (int mi = 0; mi < 2; mi++)
#pragma unroll
        for (int ni = 0; ni < 4; ni++)
#pragma unroll
            for (int q = 0; q < 4; q++) acc[mi][ni][q] = 0.f;

    int mwarp = wid >> 1;
    int nwarp = wid & 1;
    hmma_warp32(sbase, sbase + TILE_BYTES, sbase + 2*TILE_BYTES,
                sbase + 2*TILE_BYTES + HTILE_BYTES, mwarp*32, nwarp*32, lane, acc);
    __syncthreads();

    float* Csm = reinterpret_cast<float*>(dsm);
    {
        int grp = lane >> 2, qid = lane & 3;
#pragma unroll
        for (int mi = 0; mi < 2; mi++) {
#pragma unroll
            for (int ni = 0; ni < 4; ni++) {
                int r0 = mwarp*32 + mi*16 + grp;
                int c0 = nwarp*32 + ni*8 + qid*2;
                Csm[r0*68 + c0]       = acc[mi][ni][0];
                Csm[r0*68 + c0 + 1]   = acc[mi][ni][1];
                Csm[(r0+8)*68 + c0]   = acc[mi][ni][2];
                Csm[(r0+8)*68 + c0+1] = acc[mi][ni][3];
            }
        }
    }
    __syncthreads();

    {
        int n0 = nb * 64;
        size_t rbase = (size_t)mb * 128;
        for (int i = tid; i < 128*64; i += 256) {
            int r = i >> 6, c = i & 63;
            int gc = n0 + c;
            if (gc < NV)
                out[(rbase + r) * NV + gc] = Csm[r*68 + c];
        }
    }
}

// ==================== host launcher ====================
extern "C" void kernel_launch(void* const* d_in, const int* in_sizes, int n_in,
                              void* d_out, int out_size) {
    const int*   items   = (const int*)  d_in[0];
    const int*   adj     = (const int*)  d_in[1];
    const int*   alias_  = (const int*)  d_in[2];
    const int*   mask_   = (const int*)  d_in[3];
    const float* emb     = (const float*)d_in[4];
    const float* img_emb = (const float*)d_in[5];
    const float* txt_emb = (const float*)d_in[6];
    const float* W_img   = (const float*)d_in[7];
    const float* b_img   = (const float*)d_in[8];
    const float* W_txt   = (const float*)d_in[9];
    const float* b_txt   = (const float*)d_in[10];
    const float* W_fuse  = (const float*)d_in[11];
    const float* b_fuse  = (const float*)d_in[12];
    const float* a_rel   = (const float*)d_in[13];
    const float* pos_emb = (const float*)d_in[14];
    const float* w_1     = (const float*)d_in[15];
    const float* w_2     = (const float*)d_in[16];
    const float* glu1_w  = (const float*)d_in[17];
    const float* glu1_b  = (const float*)d_in[18];
    const float* glu2_w  = (const float*)d_in[19];
    float* out = (float*)d_out;

    cudaFuncSetAttribute(k4_mma, cudaFuncAttributeMaxDynamicSharedMemorySize, SMEM_HM);
    cudaFuncSetAttribute(k_mid, cudaFuncAttributeMaxDynamicSharedMemorySize, SMEM_HM);
    cudaFuncSetAttribute(k_mid12, cudaFuncAttributeMaxDynamicSharedMemorySize, SMEM_HM);

    k_prep_B<<<(NPAD*64 + 255)/256, 256>>>(emb);
    k0_combine<<<DD, DD>>>(W_img, W_txt, W_fuse, b_img, b_txt, b_fuse);
    k_prep_W<<<(6*8192 + 255)/256, 256>>>(W_fuse, w_1, glu1_w);
    k_mid<<<(BB*NN)/64, 256, SMEM_HM>>>(items, emb, img_emb, txt_emb);
    k2_attn<<<BB, 256>>>(adj, alias_, mask_, a_rel);
    k3_hsg<<<BB, DD>>>(glu2_w, glu1_b);
    k_mid12<<<(BB*LL)/64, 256, SMEM_HM>>>(pos_emb);
    k3c_select<<<BB, 256>>>(mask_, w_2);
    k_prep_A<<<(BB*64)/256, 256>>>();
    dim3 g4(NB64, BB/128);
    k4_mma<<<g4, 256, SMEM_HM>>>(out);
}

// round 16
// speedup vs baseline: 1.0033x; 1.0033x over previous
#include <cuda_runtime.h>
#include <cuda_bf16.h>
#include <cstdint>
#include <math.h>

typedef unsigned char      u8;
typedef unsigned short     u16;
typedef unsigned int       u32;
typedef unsigned long long u64;

// Problem sizes (fixed by reference)
#define BB 1024
#define NN 24
#define LL 24
#define DD 128
#define VV 40000
#define NV 39999      // V-1 output columns
#define ALPHA 0.2f
#define NEGC (-9e15f)

// HMMA tile format
#define NB4 313              // ceil(39999/128) (prep granularity)
#define NB64 625             // ceil(39999/64)  (k4 col blocks)
#define NPAD (NB4*128)       // 40064
#define TSTRIDE 272          // bytes per row (17 x 16B -> conflict-free ldmatrix)
#define TILE_BYTES (128*TSTRIDE)        // 34816 (128-row tile)
#define TILE_U4 (TILE_BYTES/16)         // 2176
#define TILE_U32 (TILE_BYTES/4)         // 8704
#define HTILE_BYTES (64*TSTRIDE)        // 17408 (64-row tile)
#define HTILE_U4 (HTILE_BYTES/16)       // 1088
#define SMEM_HM (2*TILE_BYTES + 2*HTILE_BYTES)   // 104448 -> 2 CTAs/SM

// -------- device scratch (no runtime allocations allowed) --------
__device__ float g_Wci[DD*DD];
__device__ float g_Wct[DD*DD];
__device__ float g_bcomb[DD];
__device__ float g_h[BB*NN*DD];
__device__ float g_seq[BB*LL*DD];
__device__ float g_gate[BB*LL*DD];
__device__ float g_hs[BB*DD];
__device__ float g_hsg[BB*DD];
__device__ float g_select[BB*DD];
// padded bf16 hi/lo tiles
__device__ uint4 g_Bhi4[(size_t)NB4*TILE_U4];
__device__ uint4 g_Blo4[(size_t)NB4*TILE_U4];
__device__ uint4 g_Ahi4[8*TILE_U4];
__device__ uint4 g_Alo4[8*TILE_U4];
// transposed weight tiles for mid GEMMs: [0..2]=k1 (Wfuse0,Wci,Wct), [3..4]=w_1, [5]=glu1_w
__device__ uint4 g_Wt_hi[6*TILE_U4];
__device__ uint4 g_Wt_lo[6*TILE_U4];

// ==================== helpers ====================
__device__ __forceinline__ u32 smem_u32(const void* p) {
    u32 a;
    asm("{ .reg .u64 t; cvta.to.shared.u64 t, %1; cvt.u32.u64 %0, t; }" : "=r"(a) : "l"(p));
    return a;
}
__device__ __forceinline__ void ldsm4(u32* r, u32 addr) {
    asm volatile("ldmatrix.sync.aligned.m8n8.x4.shared.b16 {%0,%1,%2,%3}, [%4];"
        : "=r"(r[0]), "=r"(r[1]), "=r"(r[2]), "=r"(r[3]) : "r"(addr));
}
__device__ __forceinline__ void mma16816(float* c, const u32* a, u32 b0, u32 b1) {
    asm volatile("mma.sync.aligned.m16n8k16.row.col.f32.bf16.bf16.f32 "
        "{%0,%1,%2,%3}, {%4,%5,%6,%7}, {%8,%9}, {%0,%1,%2,%3};"
        : "+f"(c[0]), "+f"(c[1]), "+f"(c[2]), "+f"(c[3])
        : "r"(a[0]), "r"(a[1]), "r"(a[2]), "r"(a[3]), "r"(b0), "r"(b1));
}
__device__ __forceinline__ void split_bf16(float v, u16& h, u16& l) {
    __nv_bfloat16 hb = __float2bfloat16(v);
    float rem = v - __bfloat162float(hb);
    __nv_bfloat16 lb = __float2bfloat16(rem);
    h = __bfloat16_as_ushort(hb);
    l = __bfloat16_as_ushort(lb);
}
__device__ __forceinline__ void split_pair(float v0, float v1, u32& hi, u32& lo) {
    u16 h0, l0, h1, l1;
    split_bf16(v0, h0, l0);
    split_bf16(v1, h1, l1);
    hi = (u32)h0 | ((u32)h1 << 16);
    lo = (u32)l0 | ((u32)l1 << 16);
}

// 32x32 warp tile over K=128 chunk, 3-term split-bf16.
__device__ __forceinline__ void hmma_warp32(u32 sAhi, u32 sAlo, u32 sBhi, u32 sBlo,
                                            int arow, int brow, int lane,
                                            float acc[2][4][4]) {
    u32 aoff = (u32)(arow + (lane & 15)) * TSTRIDE + ((lane >> 4) << 3) * 2;
    u32 boff = (u32)(brow + (lane & 7) + ((lane >> 4) << 3)) * TSTRIDE
             + (((lane >> 3) & 1) << 3) * 2;
#pragma unroll
    for (int ks = 0; ks < 8; ks++) {
        u32 kbyte = (u32)ks * 32;
        u32 bhi[2][4], blo[2][4];
#pragma unroll
        for (int np = 0; np < 2; np++) {
            u32 off = boff + (u32)(np*16)*TSTRIDE + kbyte;
            ldsm4(bhi[np], sBhi + off);
            ldsm4(blo[np], sBlo + off);
        }
#pragma unroll
        for (int mi = 0; mi < 2; mi++) {
            u32 ahi[4], alo[4];
            u32 off = aoff + (u32)(mi*16)*TSTRIDE + kbyte;
            ldsm4(ahi, sAhi + off);
            ldsm4(alo, sAlo + off);
#pragma unroll
            for (int ni = 0; ni < 4; ni++) {
                int np = ni >> 1;
                int s = (ni & 1) * 2;
                mma16816(acc[mi][ni], ahi, bhi[np][s], bhi[np][s+1]);
                mma16816(acc[mi][ni], ahi, blo[np][s], blo[np][s+1]);
                mma16816(acc[mi][ni], alo, bhi[np][s], bhi[np][s+1]);
            }
        }
    }
}

// ==================== K0: fold W_img/W_txt into W_fuse ====================
__global__ void k0_combine(const float* __restrict__ W_img, const float* __restrict__ W_txt,
                           const float* __restrict__ W_fuse, const float* __restrict__ b_img,
                           const float* __restrict__ b_txt, const float* __restrict__ b_fuse) {
    int k = blockIdx.x, d = threadIdx.x;
    float s1 = 0.f, s2 = 0.f;
    for (int j = 0; j < DD; j++) {
        s1 += W_img[k*DD + j] * W_fuse[(DD   + j)*DD + d];
        s2 += W_txt[k*DD + j] * W_fuse[(2*DD + j)*DD + d];
    }
    g_Wci[k*DD + d] = s1;
    g_Wct[k*DD + d] = s2;
    if (k == 0) {
        float s = b_fuse[d];
        for (int j = 0; j < DD; j++)
            s += b_img[j]*W_fuse[(DD + j)*DD + d] + b_txt[j]*W_fuse[(2*DD + j)*DD + d];
        g_bcomb[d] = s;
    }
}

// ==================== prep: transposed weight tiles (hi/lo) ====================
__global__ void k_prep_W(const float* __restrict__ W_fuse, const float* __restrict__ w_1,
                         const float* __restrict__ glu1_w) {
    int idx = blockIdx.x * 256 + threadIdx.x;
    if (idx >= 6*8192) return;
    int t = idx >> 13;
    int n = (idx >> 6) & 127;
    int c2 = idx & 63;
    int k = c2 * 2;
    float v0, v1;
    switch (t) {
        case 0: v0 = W_fuse[k*DD + n];       v1 = W_fuse[(k+1)*DD + n];       break;
        case 1: v0 = g_Wci[k*DD + n];        v1 = g_Wci[(k+1)*DD + n];        break;
        case 2: v0 = g_Wct[k*DD + n];        v1 = g_Wct[(k+1)*DD + n];        break;
        case 3: v0 = w_1[k*DD + n];          v1 = w_1[(k+1)*DD + n];          break;
        case 4: v0 = w_1[(128+k)*DD + n];    v1 = w_1[(128+k+1)*DD + n];      break;
        default: v0 = glu1_w[k*DD + n];      v1 = glu1_w[(k+1)*DD + n];       break;
    }
    u32 hi, lo;
    split_pair(v0, v1, hi, lo);
    size_t w = (size_t)t * TILE_U32 + (size_t)n * (TSTRIDE/4) + c2;
    reinterpret_cast<u32*>(g_Wt_hi)[w] = hi;
    reinterpret_cast<u32*>(g_Wt_lo)[w] = lo;
}

// ==================== k1: fused multimodal embedding (HMMA, M=64/CTA) ====================
__global__ void __launch_bounds__(256, 2) k_mid(
        const int* __restrict__ items, const float* __restrict__ emb,
        const float* __restrict__ img, const float* __restrict__ txt) {
    extern __shared__ u8 dsm[];
    __shared__ int sitem[64];
    int tid = threadIdx.x;
    int wid = tid >> 5, lane = tid & 31;
    int m0 = blockIdx.x * 64;

    if (tid < 64) sitem[tid] = items[m0 + tid];

    u32 sbase = smem_u32(dsm);
    u32 sAhi = sbase;
    u32 sAlo = sbase + HTILE_BYTES;
    u32 sWhi = sbase + 2*HTILE_BYTES;
    u32 sWlo = sbase + 2*HTILE_BYTES + TILE_BYTES;
    u32* Ahi32 = reinterpret_cast<u32*>(dsm);
    u32* Alo32 = reinterpret_cast<u32*>(dsm + HTILE_BYTES);
    uint4* Wh4 = reinterpret_cast<uint4*>(dsm + 2*HTILE_BYTES);
    uint4* Wl4 = reinterpret_cast<uint4*>(dsm + 2*HTILE_BYTES + TILE_BYTES);

    float acc[2][4][4];
#pragma unroll
    for (int mi = 0; mi < 2; mi++)
#pragma unroll
        for (int ni = 0; ni < 4; ni++)
#pragma unroll
            for (int q = 0; q < 4; q++) acc[mi][ni][q] = 0.f;

    __syncthreads();
    for (int t = 0; t < 3; t++) {
        if (t > 0) __syncthreads();
        {
            const uint4* sh = g_Wt_hi + (size_t)t * TILE_U4;
            const uint4* sl = g_Wt_lo + (size_t)t * TILE_U4;
            for (int i = tid; i < TILE_U4; i += 256) { Wh4[i] = sh[i]; Wl4[i] = sl[i]; }
        }
        const float* src = (t == 0) ? emb : (t == 1) ? img : txt;
        for (int idx = tid; idx < 4096; idx += 256) {
            int r = idx >> 6, c2 = idx & 63, c = c2*2;
            const float* p = src + (size_t)sitem[r]*DD + c;
            u32 hi, lo; split_pair(p[0], p[1], hi, lo);
            int w = r*(TSTRIDE/4) + c2;
            Ahi32[w] = hi; Alo32[w] = lo;
        }
        __syncthreads();
        hmma_warp32(sAhi, sAlo, sWhi, sWlo, (wid >> 2)*32, (wid & 3)*32, lane, acc);
    }
    __syncthreads();

    float* Csm = reinterpret_cast<float*>(dsm);
    {
        int mwarp = wid >> 2, nwarp = wid & 3;
        int grp = lane >> 2, qid = lane & 3;
#pragma unroll
        for (int mi = 0; mi < 2; mi++) {
#pragma unroll
            for (int ni = 0; ni < 4; ni++) {
                int r0 = mwarp*32 + mi*16 + grp;
                int c0 = nwarp*32 + ni*8 + qid*2;
                Csm[r0*132 + c0]       = acc[mi][ni][0];
                Csm[r0*132 + c0 + 1]   = acc[mi][ni][1];
                Csm[(r0+8)*132 + c0]   = acc[mi][ni][2];
                Csm[(r0+8)*132 + c0+1] = acc[mi][ni][3];
            }
        }
    }
    __syncthreads();
    for (int i = tid; i < 64*128; i += 256) {
        int r = i >> 7, c = i & 127;
        g_h[(size_t)(m0 + r)*DD + c] = Csm[r*132 + c] + g_bcomb[c];
    }
}

// ==================== k_mid12: fused nh+gate (2 HMMA GEMMs, nh stays in smem) ====================
__global__ void __launch_bounds__(256, 2) k_mid12(const float* __restrict__ pos_emb) {
    extern __shared__ u8 dsm[];
    int tid = threadIdx.x;
    int wid = tid >> 5, lane = tid & 31;
    int m0 = blockIdx.x * 64;

    u32 sbase = smem_u32(dsm);
    u32 sAhi = sbase;
    u32 sAlo = sbase + HTILE_BYTES;
    u32 sWhi = sbase + 2*HTILE_BYTES;
    u32 sWlo = sbase + 2*HTILE_BYTES + TILE_BYTES;
    u32* Ahi32 = reinterpret_cast<u32*>(dsm);
    u32* Alo32 = reinterpret_cast<u32*>(dsm + HTILE_BYTES);
    uint4* Wh4 = reinterpret_cast<uint4*>(dsm + 2*HTILE_BYTES);
    uint4* Wl4 = reinterpret_cast<uint4*>(dsm + 2*HTILE_BYTES + TILE_BYTES);

    int mwarp = wid >> 2, nwarp = wid & 3;
    int grp = lane >> 2, qid = lane & 3;

    float acc[2][4][4];
#pragma unroll
    for (int mi = 0; mi < 2; mi++)
#pragma unroll
        for (int ni = 0; ni < 4; ni++)
#pragma unroll
            for (int q = 0; q < 4; q++) acc[mi][ni][q] = 0.f;

    // ---- GEMM 1: nh_pre = [pos_rev | seq] @ w_1, two K=128 chunks ----
    for (int t = 0; t < 2; t++) {
        if (t > 0) __syncthreads();
        {
            const uint4* sh = g_Wt_hi + (size_t)(3 + t) * TILE_U4;
            const uint4* sl = g_Wt_lo + (size_t)(3 + t) * TILE_U4;
            for (int i = tid; i < TILE_U4; i += 256) { Wh4[i] = sh[i]; Wl4[i] = sl[i]; }
        }
        for (int idx = tid; idx < 4096; idx += 256) {
            int r = idx >> 6, c2 = idx & 63, c = c2*2;
            int row = m0 + r;
            const float* p;
            if (t == 0) { int l = row % LL; p = pos_emb + (size_t)(LL-1-l)*DD + c; }
            else        { p = g_seq + (size_t)row*DD + c; }
            u32 hi, lo; split_pair(p[0], p[1], hi, lo);
            int w = r*(TSTRIDE/4) + c2;
            Ahi32[w] = hi; Alo32[w] = lo;
        }
        __syncthreads();
        hmma_warp32(sAhi, sAlo, sWhi, sWlo, mwarp*32, nwarp*32, lane, acc);
    }
    __syncthreads();   // all MMA reads of A/W done

    // ---- nh = tanh(acc): split-store fragments directly into A slots; load glu1_w ----
    {
#pragma unroll
        for (int mi = 0; mi < 2; mi++) {
#pragma unroll
            for (int ni = 0; ni < 4; ni++) {
                int r0 = mwarp*32 + mi*16 + grp;
                int c2 = (nwarp*32 + ni*8 + qid*2) >> 1;
                u32 hi, lo;
                split_pair(tanhf(acc[mi][ni][0]), tanhf(acc[mi][ni][1]), hi, lo);
                Ahi32[r0*(TSTRIDE/4) + c2] = hi;
                Alo32[r0*(TSTRIDE/4) + c2] = lo;
                split_pair(tanhf(acc[mi][ni][2]), tanhf(acc[mi][ni][3]), hi, lo);
                Ahi32[(r0+8)*(TSTRIDE/4) + c2] = hi;
                Alo32[(r0+8)*(TSTRIDE/4) + c2] = lo;
            }
        }
        const uint4* sh = g_Wt_hi + (size_t)5 * TILE_U4;
        const uint4* sl = g_Wt_lo + (size_t)5 * TILE_U4;
        for (int i = tid; i < TILE_U4; i += 256) { Wh4[i] = sh[i]; Wl4[i] = sl[i]; }
    }
    __syncthreads();

    // ---- GEMM 2: gate_pre = nh @ glu1_w ----
#pragma unroll
    for (int mi = 0; mi < 2; mi++)
#pragma unroll
        for (int ni = 0; ni < 4; ni++)
#pragma unroll
            for (int q = 0; q < 4; q++) acc[mi][ni][q] = 0.f;
    hmma_warp32(sAhi, sAlo, sWhi, sWlo, mwarp*32, nwarp*32, lane, acc);
    __syncthreads();

    // ---- epilogue: gate = sigmoid(acc + hsg[b]) ----
    float* Csm = reinterpret_cast<float*>(dsm);
    {
#pragma unroll
        for (int mi = 0; mi < 2; mi++) {
#pragma unroll
            for (int ni = 0; ni < 4; ni++) {
                int r0 = mwarp*32 + mi*16 + grp;
                int c0 = nwarp*32 + ni*8 + qid*2;
                Csm[r0*132 + c0]       = acc[mi][ni][0];
                Csm[r0*132 + c0 + 1]   = acc[mi][ni][1];
                Csm[(r0+8)*132 + c0]   = acc[mi][ni][2];
                Csm[(r0+8)*132 + c0+1] = acc[mi][ni][3];
            }
        }
    }
    __syncthreads();
    for (int i = tid; i < 64*128; i += 256) {
        int r = i >> 7, c = i & 127;
        size_t row = (size_t)(m0 + r);
        int b = (int)(row / LL);
        float v = Csm[r*132 + c] + g_hsg[(size_t)b*DD + c];
        g_gate[row*DD + c] = 1.f / (1.f + expf(-v));
    }
}

// ==================== K2: RGAT attention (select-first dot + array butterfly) ====================
__global__ void __launch_bounds__(256, 3) k2_attn(const int* __restrict__ adj,
                        const int* __restrict__ alias_,
                        const int* __restrict__ mask_, const float* __restrict__ a_rel) {
    __shared__ float hsm[NN*DD];
    __shared__ float hag[NN*DD];
    __shared__ float logit[NN*NN];
    __shared__ float arel[4*DD];
    __shared__ int sadj[NN*NN];
    __shared__ int salias[LL];
    __shared__ int smask[LL];
    __shared__ float4 hpart4[256];
    __shared__ float sdenom;
    int b = blockIdx.x, tid = threadIdx.x;
    int wid = tid >> 5, lane = tid & 31;

    {
        const float4* src = reinterpret_cast<const float4*>(&g_h[(size_t)b*NN*DD]);
        float4* dst = reinterpret_cast<float4*>(hsm);
        for (int i = tid; i < NN*DD/4; i += 256) dst[i] = src[i];
        const float4* asrc = reinterpret_cast<const float4*>(a_rel);
        float4* adst = reinterpret_cast<float4*>(arel);
        if (tid < 128) adst[tid] = asrc[tid];
        const int* ja = adj + (size_t)b*NN*NN;
        for (int i = tid; i < NN*NN; i += 256) sadj[i] = ja[i];
    }
    if (tid < LL) { salias[tid] = alias_[b*LL + tid]; smask[tid] = mask_[b*LL + tid]; }
    if (tid == 0) {
        int ms = 0;
        for (int l = 0; l < LL; l++) ms += mask_[b*LL + l];
        sdenom = fmaxf((float)ms, 1.f);
    }
    __syncthreads();

    // ---- edge scores: warp per i; select relation first, one dot per j;
    //      per-lane partials accumulate in a register array, then ONE 5-stage
    //      butterfly reduces all 24 j's simultaneously ----
    {
        const float4* h4 = reinterpret_cast<const float4*>(hsm);
        const float4* a4 = reinterpret_cast<const float4*>(arel);
        for (int i = wid; i < NN; i += 8) {
            float4 hi = h4[i*32 + lane];
            float4 a0 = a4[0*32 + lane], a1 = a4[1*32 + lane];
            float4 a2 = a4[2*32 + lane], a3 = a4[3*32 + lane];
            float4 w0, w1, w2, w3;
            w0.x = hi.x*a0.x; w0.y = hi.y*a0.y; w0.z = hi.z*a0.z; w0.w = hi.w*a0.w;
            w1.x = hi.x*a1.x; w1.y = hi.y*a1.y; w1.z = hi.z*a1.z; w1.w = hi.w*a1.w;
            w2.x = hi.x*a2.x; w2.y = hi.y*a2.y; w2.z = hi.z*a2.z; w2.w = hi.w*a2.w;
            w3.x = hi.x*a3.x; w3.y = hi.y*a3.y; w3.z = hi.z*a3.z; w3.w = hi.w*a3.w;
            float part[NN];
#pragma unroll
            for (int j = 0; j < NN; j++) {
                float4 hj = h4[j*32 + lane];
                int r = sadj[i*NN + j];
                float4 ws = (r == 1) ? w0 : (r == 2) ? w1 : (r == 3) ? w2 : w3;
                part[j] = ws.x*hj.x + ws.y*hj.y + ws.z*hj.z + ws.w*hj.w;
            }
#pragma unroll
            for (int off = 16; off > 0; off >>= 1)
#pragma unroll
                for (int j = 0; j < NN; j++)
                    part[j] += __shfl_xor_sync(0xffffffffu, part[j], off);
#pragma unroll
            for (int j = 0; j < NN; j++) {
                if (lane == j) {
                    int r = sadj[i*NN + j];
                    float e = (part[j] > 0.f) ? part[j] : ALPHA * part[j];
                    logit[i*NN + j] = (r == 0) ? NEGC : e;
                }
            }
        }
    }
    __syncthreads();

    // ---- row softmax ----
    if (tid < NN) {
        float m = -INFINITY;
#pragma unroll
        for (int j = 0; j < NN; j++) m = fmaxf(m, logit[tid*NN + j]);
        float ex[NN]; float ssum = 0.f;
#pragma unroll
        for (int j = 0; j < NN; j++) { ex[j] = __expf(logit[tid*NN + j] - m); ssum += ex[j]; }
        float inv = 1.f / ssum;
#pragma unroll
        for (int j = 0; j < NN; j++) logit[tid*NN + j] = ex[j] * inv;
    }
    __syncthreads();

    // ---- aggregate: hag = att @ h ----
    {
        const float4* h4 = reinterpret_cast<const float4*>(hsm);
        float4* hag4 = reinterpret_cast<float4*>(hag);
        for (int idx = tid; idx < NN*32; idx += 256) {
            int i = idx >> 5;
            int d4 = idx & 31;
            float4 s = make_float4(0.f, 0.f, 0.f, 0.f);
#pragma unroll
            for (int j = 0; j < NN; j++) {
                float w = logit[i*NN + j];
                float4 hv = h4[j*32 + d4];
                s.x += w*hv.x; s.y += w*hv.y; s.z += w*hv.z; s.w += w*hv.w;
            }
            hag4[idx] = s;
        }
    }
    __syncthreads();

    // ---- seq = hag[alias]; hs = masked mean ----
    {
        const float4* hag4 = reinterpret_cast<const float4*>(hag);
        float4* seq4 = reinterpret_cast<float4*>(&g_seq[(size_t)b*LL*DD]);
        float4 part = make_float4(0.f, 0.f, 0.f, 0.f);
        for (int idx = tid; idx < LL*32; idx += 256) {
            int l = idx >> 5;
            int d4 = idx & 31;
            float4 v = hag4[salias[l]*32 + d4];
            seq4[idx] = v;
            float mf = (float)smask[l];
            part.x += v.x*mf; part.y += v.y*mf; part.z += v.z*mf; part.w += v.w*mf;
        }
        hpart4[tid] = part;
    }
    __syncthreads();
    if (tid < 32) {
        float4 s = make_float4(0.f, 0.f, 0.f, 0.f);
#pragma unroll
        for (int w = 0; w < 8; w++) {
            float4 v = hpart4[tid + 32*w];
            s.x += v.x; s.y += v.y; s.z += v.z; s.w += v.w;
        }
        float inv = 1.f / sdenom;
        s.x *= inv; s.y *= inv; s.z *= inv; s.w *= inv;
        reinterpret_cast<float4*>(&g_hs[(size_t)b*DD])[tid] = s;
    }
}

// ==================== K3h: hsg = glu1_b + hs @ glu2_w ====================
__global__ void k3_hsg(const float* __restrict__ glu2_w, const float* __restrict__ glu1_b) {
    __shared__ float shs[DD];
    int b = blockIdx.x, d = threadIdx.x;
    shs[d] = g_hs[(size_t)b*DD + d];
    __syncthreads();
    float s = glu1_b[d];
    for (int k = 0; k < DD; k++) s += shs[k] * glu2_w[k*DD + d];
    g_hsg[(size_t)b*DD + d] = s;
}

// ==================== K3c: beta = gate@w_2 ; select = sum_l beta*seq*mask ====================
__global__ void k3c_select(const int* __restrict__ mask_, const float* __restrict__ w_2) {
    __shared__ float beta[LL];
    __shared__ float sw2[DD];
    __shared__ int smask[LL];
    int b = blockIdx.x, tid = threadIdx.x;
    if (tid < DD) sw2[tid] = w_2[tid];
    if (tid < LL) smask[tid] = mask_[b*LL + tid];
    __syncthreads();
    int wid = tid >> 5, lane = tid & 31;
    for (int l = wid; l < LL; l += 8) {
        float s = 0.f;
        const float* g = &g_gate[((size_t)b*LL + l)*DD];
        for (int d = lane; d < DD; d += 32) s += g[d] * sw2[d];
#pragma unroll
        for (int o = 16; o > 0; o >>= 1) s += __shfl_xor_sync(0xffffffffu, s, o);
        if (lane == 0) beta[l] = s;
    }
    __syncthreads();
    if (tid < DD) {
        float s = 0.f;
        for (int l = 0; l < LL; l++)
            s += beta[l] * (float)smask[l] * g_seq[((size_t)b*LL + l)*DD + tid];
        g_select[(size_t)b*DD + tid] = s;
    }
}

// ==================== prep: emb -> padded bf16 hi/lo tiles ====================
__global__ void k_prep_B(const float* __restrict__ emb) {
    int idx = blockIdx.x * 256 + threadIdx.x;
    if (idx >= NPAD * 64) return;
    int r = idx >> 6;
    int c2 = idx & 63;
    int c = c2 * 2;
    float v0 = 0.f, v1 = 0.f;
    if (r < NV) {
        const float* p = emb + (size_t)(r + 1) * DD + c;
        v0 = p[0]; v1 = p[1];
    }
    u32 hi, lo; split_pair(v0, v1, hi, lo);
    size_t w = (size_t)(r >> 7) * TILE_U32 + (size_t)(r & 127) * (TSTRIDE/4) + c2;
    reinterpret_cast<u32*>(g_Bhi4)[w] = hi;
    reinterpret_cast<u32*>(g_Blo4)[w] = lo;
}

// ==================== prep: select -> padded bf16 hi/lo tiles ====================
__global__ void k_prep_A() {
    int idx = blockIdx.x * 256 + threadIdx.x;
    int row = idx >> 6;
    int c2 = idx & 63;
    int c = c2 * 2;
    float v0 = g_select[(size_t)row * DD + c];
    float v1 = g_select[(size_t)row * DD + c + 1];
    u32 hi, lo; split_pair(v0, v1, hi, lo);
    size_t w = (size_t)(row >> 7) * TILE_U32 + (size_t)(row & 127) * (TSTRIDE/4) + c2;
    reinterpret_cast<u32*>(g_Ahi4)[w] = hi;
    reinterpret_cast<u32*>(g_Alo4)[w] = lo;
}

// ==================== K4: scores GEMM, 128x64 tile, 2 CTAs/SM ====================
__global__ void __launch_bounds__(256, 2) k4_mma(float* __restrict__ out) {
    extern __shared__ u8 dsm[];
    int tid = threadIdx.x;
    int wid = tid >> 5;
    int lane = tid & 31;
    int nb = blockIdx.x;
    int mb = blockIdx.y;

    {
        const uint4* sAh = g_Ahi4 + (size_t)mb * TILE_U4;
        const uint4* sAl = g_Alo4 + (size_t)mb * TILE_U4;
        size_t boffg = (size_t)(nb >> 1) * TILE_U4 + (size_t)(nb & 1) * HTILE_U4;
        const uint4* sBh = g_Bhi4 + boffg;
        const uint4* sBl = g_Blo4 + boffg;
        uint4* dsm4 = reinterpret_cast<uint4*>(dsm);
        for (int i = tid; i < TILE_U4; i += 256) {
            dsm4[i] = sAh[i];
            dsm4[TILE_U4 + i] = sAl[i];
        }
        for (int i = tid; i < HTILE_U4; i += 256) {
            dsm4[2*TILE_U4 + i] = sBh[i];
            dsm4[2*TILE_U4 + HTILE_U4 + i] = sBl[i];
        }
    }
    __syncthreads();

    u32 sbase = smem_u32(dsm);
    float acc[2][4][4];
#pragma unroll
    for (int mi = 0; mi < 2; mi++)
#pragma unroll
        for (int ni = 0; ni < 4; ni++)
#pragma unroll
            for (int q = 0; q < 4; q++) acc[mi][ni][q] = 0.f;

    int mwarp = wid >> 1;
    int nwarp = wid & 1;
    hmma_warp32(sbase, sbase + TILE_BYTES, sbase + 2*TILE_BYTES,
                sbase + 2*TILE_BYTES + HTILE_BYTES, mwarp*32, nwarp*32, lane, acc);
    __syncthreads();

    float* Csm = reinterpret_cast<float*>(dsm);
    {
        int grp = lane >> 2, qid = lane & 3;
#pragma unroll
        for (int mi = 0; mi < 2; mi++) {
#pragma unroll
            for (int ni = 0; ni < 4; ni++) {
                int r0 = mwarp*32 + mi*16 + grp;
                int c0 = nwarp*32 + ni*8 + qid*2;
                Csm[r0*68 + c0]       = acc[mi][ni][0];
                Csm[r0*68 + c0 + 1]   = acc[mi][ni][1];
                Csm[(r0+8)*68 + c0]   = acc[mi][ni][2];
                Csm[(r0+8)*68 + c0+1] = acc[mi][ni][3];
            }
        }
    }
    __syncthreads();

    {
        int n0 = nb * 64;
        size_t rbase = (size_t)mb * 128;
        for (int i = tid; i < 128*64; i += 256) {
            int r = i >> 6, c = i & 63;
            int gc = n0 + c;
            if (gc < NV)
                out[(rbase + r) * NV + gc] = Csm[r*68 + c];
        }
    }
}

// ==================== host launcher ====================
extern "C" void kernel_launch(void* const* d_in, const int* in_sizes, int n_in,
                              void* d_out, int out_size) {
    const int*   items   = (const int*)  d_in[0];
    const int*   adj     = (const int*)  d_in[1];
    const int*   alias_  = (const int*)  d_in[2];
    const int*   mask_   = (const int*)  d_in[3];
    const float* emb     = (const float*)d_in[4];
    const float* img_emb = (const float*)d_in[5];
    const float* txt_emb = (const float*)d_in[6];
    const float* W_img   = (const float*)d_in[7];
    const float* b_img   = (const float*)d_in[8];
    const float* W_txt   = (const float*)d_in[9];
    const float* b_txt   = (const float*)d_in[10];
    const float* W_fuse  = (const float*)d_in[11];
    const float* b_fuse  = (const float*)d_in[12];
    const float* a_rel   = (const float*)d_in[13];
    const float* pos_emb = (const float*)d_in[14];
    const float* w_1     = (const float*)d_in[15];
    const float* w_2     = (const float*)d_in[16];
    const float* glu1_w  = (const float*)d_in[17];
    const float* glu1_b  = (const float*)d_in[18];
    const float* glu2_w  = (const float*)d_in[19];
    float* out = (float*)d_out;

    cudaFuncSetAttribute(k4_mma, cudaFuncAttributeMaxDynamicSharedMemorySize, SMEM_HM);
    cudaFuncSetAttribute(k_mid, cudaFuncAttributeMaxDynamicSharedMemorySize, SMEM_HM);
    cudaFuncSetAttribute(k_mid12, cudaFuncAttributeMaxDynamicSharedMemorySize, SMEM_HM);

    k_prep_B<<<(NPAD*64 + 255)/256, 256>>>(emb);
    k0_combine<<<DD, DD>>>(W_img, W_txt, W_fuse, b_img, b_txt, b_fuse);
    k_prep_W<<<(6*8192 + 255)/256, 256>>>(W_fuse, w_1, glu1_w);
    k_mid<<<(BB*NN)/64, 256, SMEM_HM>>>(items, emb, img_emb, txt_emb);
    k2_attn<<<BB, 256>>>(adj, alias_, mask_, a_rel);
    k3_hsg<<<BB, DD>>>(glu2_w, glu1_b);
    k_mid12<<<(BB*LL)/64, 256, SMEM_HM>>>(pos_emb);
    k3c_select<<<BB, 256>>>(mask_, w_2);
    k_prep_A<<<(BB*64)/256, 256>>>();
    dim3 g4(NB64, BB/128);
    k4_mma<<<g4, 256, SMEM_HM>>>(out);
}